// round 3
// baseline (speedup 1.0000x reference)
#include <cuda_runtime.h>
#include <math.h>
#include <stdint.h>

#define B 2048
#define C 50257
#define THREADS 512

// Per-row partial results (scratch — __device__ globals per allocation rules)
__device__ float g_l1[B];
__device__ float g_ce[B];

struct Acc {
    float m;    // running max
    float s;    // running sum of exp(x - m)
    float sum;  // row sum
    float l1;   // L1 partial (generic term at every column incl. label; fixed later)
};

__device__ __forceinline__ void acc_elem(Acc& a, float x) {
    a.sum += x;
    a.l1 += (x > 0.f) ? 10.f * fabsf(1.f - x) : 10.f;
    if (x > a.m) {
        a.s = a.s * __expf(a.m - x) + 1.f;
        a.m = x;
    } else {
        a.s += __expf(x - a.m);
    }
}

__global__ __launch_bounds__(THREADS)
void row_kernel(const float* __restrict__ out, const int* __restrict__ labels) {
    const int row = blockIdx.x;
    const int tid = threadIdx.x;
    const float* rp = out + (long long)row * C;

    Acc a;
    a.m = -INFINITY; a.s = 0.f; a.sum = 0.f; a.l1 = 0.f;

    // Alignment peel: rp is 4B-aligned; peel to 16B boundary for float4
    const int mis = (int)(((uintptr_t)rp >> 2) & 3);     // floats past a 16B boundary
    const int pre = (4 - mis) & 3;
    if (tid < pre) acc_elem(a, __ldg(rp + tid));

    const float4* rp4 = (const float4*)(rp + pre);
    const int n4 = (C - pre) >> 2;
    for (int i = tid; i < n4; i += THREADS) {
        float4 v = __ldg(rp4 + i);
        acc_elem(a, v.x);
        acc_elem(a, v.y);
        acc_elem(a, v.z);
        acc_elem(a, v.w);
    }

    const int tail_start = pre + (n4 << 2);
    const int tail = C - tail_start;
    if (tid < tail) acc_elem(a, __ldg(rp + tail_start + tid));

    __shared__ float sh_a[THREADS];
    __shared__ float sh_b[THREADS];
    __shared__ float sh_c[THREADS];

    // 1) reduce max
    sh_a[tid] = a.m;
    __syncthreads();
    for (int off = THREADS / 2; off > 0; off >>= 1) {
        if (tid < off) sh_a[tid] = fmaxf(sh_a[tid], sh_a[tid + off]);
        __syncthreads();
    }
    const float M = sh_a[0];
    __syncthreads();

    // 2) reduce rescaled expsum, row sum, l1
    sh_a[tid] = a.s * __expf(a.m - M);  // m=-inf,s=0 -> 0, safe
    sh_b[tid] = a.sum;
    sh_c[tid] = a.l1;
    __syncthreads();
    for (int off = THREADS / 2; off > 0; off >>= 1) {
        if (tid < off) {
            sh_a[tid] += sh_a[tid + off];
            sh_b[tid] += sh_b[tid + off];
            sh_c[tid] += sh_c[tid + off];
        }
        __syncthreads();
    }

    if (tid == 0) {
        const float S = sh_a[0];
        const float rowsum = sh_b[0];
        float l1row = sh_c[0];

        const int lbl = labels[row];
        const float g = __ldg(rp + lbl);

        // remove generic term added in the loop at the label column
        const float wrong = (g > 0.f) ? 10.f * fabsf(1.f - g) : 10.f;
        // correct label term
        const float mean = rowsum * (1.f / (float)C);
        const float row_val = fmaxf(fabsf(mean), fabsf(g)) * 10.f;
        const float temp_out_lbl = (g > 0.f) ? -10.f * g : 0.f;
        const float right = fabsf(temp_out_lbl - row_val);
        l1row = l1row - wrong + right;

        g_l1[row] = l1row;
        g_ce[row] = (M + logf(S)) - g;
    }
}

__global__ __launch_bounds__(1024)
void final_kernel(float* __restrict__ d_out) {
    const int tid = threadIdx.x;
    __shared__ float sh_l1[1024];
    __shared__ float sh_ce[1024];

    sh_l1[tid] = g_l1[tid] + g_l1[tid + 1024];
    sh_ce[tid] = g_ce[tid] + g_ce[tid + 1024];
    __syncthreads();
    for (int off = 512; off > 0; off >>= 1) {
        if (tid < off) {
            sh_l1[tid] += sh_l1[tid + off];
            sh_ce[tid] += sh_ce[tid + off];
        }
        __syncthreads();
    }
    if (tid == 0) {
        const float l1_mean = sh_l1[0] / ((float)B * (float)C);
        const float ce_mean = sh_ce[0] / (float)B;
        d_out[0] = 0.5f * l1_mean + 0.5f * ce_mean;
    }
}

extern "C" void kernel_launch(void* const* d_in, const int* in_sizes, int n_in,
                              void* d_out, int out_size) {
    const float* out = (const float*)d_in[0];
    const int* labels = (const int*)d_in[1];
    float* res = (float*)d_out;

    row_kernel<<<B, THREADS>>>(out, labels);
    final_kernel<<<1, 1024>>>(res);
}

// round 4
// speedup vs baseline: 1.8608x; 1.8608x over previous
#include <cuda_runtime.h>
#include <math.h>
#include <stdint.h>

#define B 2048
#define C 50257
#define THREADS 512

// Per-row partials + completion counter (device globals: allocation-guard-safe)
__device__ float g_l1[B];
__device__ float g_ce[B];
__device__ unsigned int g_count = 0;   // self-resetting via atomicInc wrap

__global__ __launch_bounds__(THREADS)
void fused_kernel(const float* __restrict__ out, const int* __restrict__ labels,
                  float* __restrict__ res) {
    const int row = blockIdx.x;
    const int tid = threadIdx.x;
    const float* rp = out + (long long)row * C;

    float sum = 0.f;   // row sum
    float l1  = 0.f;   // unscaled L1 generic term
    float es  = 0.f;   // sum of exp(x)

    // Alignment peel to 16B for float4 (row base is only 4B-aligned: C odd)
    const int mis = (int)(((uintptr_t)rp >> 2) & 3);
    const int pre = (4 - mis) & 3;
    if (tid < pre) {
        float x = __ldg(rp + tid);
        sum += x;
        l1  += (x > 0.f) ? fabsf(1.f - x) : 1.f;
        es  += __expf(x);
    }

    const float4* rp4 = (const float4*)(rp + pre);
    const int n4 = (C - pre) >> 2;
    for (int i = tid; i < n4; i += THREADS) {
        float4 v = __ldg(rp4 + i);
        // branchless, no cross-element dependency except the adds
        sum += v.x + v.y + v.z + v.w;
        l1  += (v.x > 0.f) ? fabsf(1.f - v.x) : 1.f;
        l1  += (v.y > 0.f) ? fabsf(1.f - v.y) : 1.f;
        l1  += (v.z > 0.f) ? fabsf(1.f - v.z) : 1.f;
        l1  += (v.w > 0.f) ? fabsf(1.f - v.w) : 1.f;
        es  += __expf(v.x) + __expf(v.y) + __expf(v.z) + __expf(v.w);
    }

    const int tail_start = pre + (n4 << 2);
    if (tid < C - tail_start) {
        float x = __ldg(rp + tail_start + tid);
        sum += x;
        l1  += (x > 0.f) ? fabsf(1.f - x) : 1.f;
        es  += __expf(x);
    }

    // Block reduction of (sum, l1, es)
    __shared__ float sh_a[THREADS];
    __shared__ float sh_b[THREADS];
    __shared__ float sh_c[THREADS];
    sh_a[tid] = sum; sh_b[tid] = l1; sh_c[tid] = es;
    __syncthreads();
    for (int off = THREADS / 2; off > 0; off >>= 1) {
        if (tid < off) {
            sh_a[tid] += sh_a[tid + off];
            sh_b[tid] += sh_b[tid + off];
            sh_c[tid] += sh_c[tid + off];
        }
        __syncthreads();
    }

    __shared__ bool s_last;
    if (tid == 0) {
        const float rowsum = sh_a[0];
        float l1row = sh_b[0];
        const float S = sh_c[0];

        const int lbl = labels[row];
        const float g = __ldg(rp + lbl);

        // remove generic term at the label column, add the real one
        const float wrong = (g > 0.f) ? fabsf(1.f - g) : 1.f;   // unscaled
        const float mean = rowsum * (1.f / (float)C);
        const float row_val = fmaxf(fabsf(mean), fabsf(g)) * 10.f;
        const float temp_out_lbl = (g > 0.f) ? -10.f * g : 0.f;
        const float right = fabsf(temp_out_lbl - row_val);

        g_l1[row] = (l1row - wrong) * 10.f + right;
        g_ce[row] = logf(S) - g;

        __threadfence();
        // self-resetting: wraps back to 0 when old == B-1
        s_last = (atomicInc(&g_count, B - 1) == B - 1);
    }
    __syncthreads();

    // Last block performs the deterministic final reduction (fixed read order)
    if (s_last) {
        float a = 0.f, b = 0.f;
        #pragma unroll
        for (int k = 0; k < B / THREADS; k++) {
            a += g_l1[tid + k * THREADS];
            b += g_ce[tid + k * THREADS];
        }
        sh_a[tid] = a; sh_b[tid] = b;
        __syncthreads();
        for (int off = THREADS / 2; off > 0; off >>= 1) {
            if (tid < off) {
                sh_a[tid] += sh_a[tid + off];
                sh_b[tid] += sh_b[tid + off];
            }
            __syncthreads();
        }
        if (tid == 0) {
            const float l1_mean = sh_a[0] / ((float)B * (float)C);
            const float ce_mean = sh_b[0] / (float)B;
            res[0] = 0.5f * l1_mean + 0.5f * ce_mean;
        }
    }
}

extern "C" void kernel_launch(void* const* d_in, const int* in_sizes, int n_in,
                              void* d_out, int out_size) {
    const float* out = (const float*)d_in[0];
    const int* labels = (const int*)d_in[1];
    float* res = (float*)d_out;

    fused_kernel<<<B, THREADS>>>(out, labels, res);
}